// round 8
// baseline (speedup 1.0000x reference)
#include <cuda_runtime.h>
#include <cuda_fp16.h>
#include <math.h>
#include <stdint.h>

#define TT     64
#define BBATCH 1024
#define DET    512
#define STO    64
#define EMBD   1024
#define ACTD   6
#define MLPD   512
#define COUT   896
#define NCTA   148

// ---------------- persistent scratch ----------------------------------------
__device__ __align__(16) __half g_Wi16 [512 * 128];
__device__ __align__(16) __half g_Wg16 [2 * 1536 * 512];   // gate-interleaved W_ih|W_hh
__device__ __align__(16) __half g_Wp116[512 * 512];
__device__ __align__(16) __half g_Wq116[512 * 1536];
__device__ __align__(16) __half g_Wp216[128 * 512];
__device__ __align__(16) __half g_Wq216[128 * 512];
__device__ __align__(16) __half g_x16  [BBATCH * 512];
__device__ __align__(16) __half g_det16[BBATCH * 512];
__device__ __align__(16) __half g_p116 [BBATCH * 512];
__device__ __align__(16) __half g_q116 [BBATCH * 512];
__device__ __align__(16) float  g_deter[2 * BBATCH * 512];
__device__ __align__(16) float  g_stoc [2 * BBATCH * 64];

// grid barrier state
__device__ unsigned g_barcnt;
__device__ volatile unsigned g_barsense;

// ---------------- math ------------------------------------------------------
__device__ __forceinline__ float eluf(float x)  { return x > 0.f ? x : expm1f(x); }
__device__ __forceinline__ float sigm(float x)  { return 1.f / (1.f + expf(-x)); }
__device__ __forceinline__ float softp(float x) { return x > 0.f ? x + log1pf(expf(-x)) : log1pf(expf(x)); }

// ---------------- grid barrier ----------------------------------------------
__device__ __forceinline__ void grid_bar(unsigned& tgt) {
    __syncthreads();
    if (threadIdx.x == 0) {
        ++tgt;
        __threadfence();
        if (atomicAdd(&g_barcnt, 1u) == NCTA - 1) {
            g_barcnt = 0;
            __threadfence();
            g_barsense = tgt;
        } else {
            while (g_barsense != tgt) __nanosleep(32);
            __threadfence();
        }
    }
    __syncthreads();
}

// ---------------- MMA primitives --------------------------------------------
__device__ __forceinline__ void ldm_x4(uint32_t* r, const void* p) {
    uint32_t a;
    asm("{ .reg .u64 t; cvta.to.shared.u64 t, %1; cvt.u32.u64 %0, t; }" : "=r"(a) : "l"(p));
    asm volatile("ldmatrix.sync.aligned.m8n8.x4.shared.b16 {%0,%1,%2,%3}, [%4];"
                 : "=r"(r[0]), "=r"(r[1]), "=r"(r[2]), "=r"(r[3]) : "r"(a));
}
__device__ __forceinline__ void ldm_x2(uint32_t* r, const void* p) {
    uint32_t a;
    asm("{ .reg .u64 t; cvta.to.shared.u64 t, %1; cvt.u32.u64 %0, t; }" : "=r"(a) : "l"(p));
    asm volatile("ldmatrix.sync.aligned.m8n8.x2.shared.b16 {%0,%1}, [%2];"
                 : "=r"(r[0]), "=r"(r[1]) : "r"(a));
}
__device__ __forceinline__ void mma16816(float* c, const uint32_t* a, const uint32_t* b) {
    asm volatile(
        "mma.sync.aligned.m16n8k16.row.col.f32.f16.f16.f32 "
        "{%0,%1,%2,%3}, {%4,%5,%6,%7}, {%8,%9}, {%0,%1,%2,%3};"
        : "+f"(c[0]), "+f"(c[1]), "+f"(c[2]), "+f"(c[3])
        : "r"(a[0]), "r"(a[1]), "r"(a[2]), "r"(a[3]), "r"(b[0]), "r"(b[1]));
}

// ---------------- A-tile sources --------------------------------------------
#define SRC_F16    0
#define SRC_INPUT  2
#define SRC_CONCAT 3

template<int ASRC, int BW>
__device__ __forceinline__ void fetch_tiles64(
    int k0, int rowBase, int colBase,
    const __half* Af16, int lda,
    const float* Aa, const float* Ab, const float* nt,
    const __half* Bw, int ldb,
    uint32_t* aA, uint32_t* aB)
{
    const int tid = threadIdx.x;
#pragma unroll
    for (int i = 0; i < 8; i++) {
        int w = tid + i * 256;
        int row = w >> 5, kp = w & 31;
        int b = rowBase + row;
        int k = k0 + kp * 2;
        __half2 v;
        if (ASRC == SRC_F16) {
            v = *(const __half2*)(Af16 + (size_t)b * lda + k);
        } else if (ASRC == SRC_CONCAT) {
            if (k < DET) {
                v = *(const __half2*)(Af16 + (size_t)b * DET + k);
            } else {
                float2 f = *(const float2*)(Aa + (size_t)b * EMBD + (k - DET));
                v = __floats2half2_rn(f.x, f.y);
            }
        } else { // SRC_INPUT
            float s = nt[b];
            float lo = (k < STO) ? Aa[b * STO + k] * s
                     : ((k < STO + ACTD) ? Ab[b * ACTD + (k - STO)] : 0.f);
            int k1 = k + 1;
            float hi = (k1 < STO) ? Aa[b * STO + k1] * s
                     : ((k1 < STO + ACTD) ? Ab[b * ACTD + (k1 - STO)] : 0.f);
            v = __floats2half2_rn(lo, hi);
        }
        aA[i] = *(uint32_t*)&v;
    }
#pragma unroll
    for (int i = 0; i < BW; i++) {
        int w = tid + i * 256;
        int row = w >> 5, kp = w & 31;
        __half2 v = *(const __half2*)(Bw + (size_t)(colBase + row) * ldb + k0 + kp * 2);
        aB[i] = *(uint32_t*)&v;
    }
}

// ---- C[64 x NCOLS] = A[64xK] * B[NCOLS x K]^T ------------------------------
template<int NCOLS, int ASRC>
__device__ __forceinline__ void gemm_core64(
    int kchunks,
    const __half* Af16, int lda,
    const float* Aa, const float* Ab, const float* nt,
    const __half* Bw, int ldb,
    int rowBase, int colBase,
    __half (*sA)[72], __half (*sB)[72],
    float* cacc)
{
    constexpr int BW = NCOLS / 8;
    constexpr int NT = NCOLS / 16;
    const int tid = threadIdx.x, lane = tid & 31, w = tid >> 5;
    const int mrow = (w & 3) * 16;
    const int ncol = (w >> 2) * (NCOLS / 2);

#pragma unroll
    for (int i = 0; i < NT * 4; i++) cacc[i] = 0.f;

    uint32_t aA[8], aB[BW];
    fetch_tiles64<ASRC, BW>(0, rowBase, colBase, Af16, lda, Aa, Ab, nt, Bw, ldb, aA, aB);

    for (int c = 0; c < kchunks; c++) {
#pragma unroll
        for (int i = 0; i < 8; i++) {
            int ww = tid + i * 256;
            *(uint32_t*)&sA[ww >> 5][(ww & 31) * 2] = aA[i];
        }
#pragma unroll
        for (int i = 0; i < BW; i++) {
            int ww = tid + i * 256;
            *(uint32_t*)&sB[ww >> 5][(ww & 31) * 2] = aB[i];
        }
        __syncthreads();
#pragma unroll
        for (int kk = 0; kk < 4; kk++) {
            int kb = kk * 16;
            uint32_t afr[4];
            ldm_x4(afr, &sA[mrow + (lane & 15)][kb + ((lane >> 4) << 3)]);
            uint32_t bfr[NT][2];
#pragma unroll
            for (int nt2 = 0; nt2 < NT; nt2++)
                ldm_x2(bfr[nt2], &sB[ncol + nt2 * 8 + (lane & 7)][kb + (((lane >> 3) & 1) << 3)]);
#pragma unroll
            for (int nt2 = 0; nt2 < NT; nt2++)
                mma16816(cacc + nt2 * 4, afr, bfr[nt2]);
        }
        if (c + 1 < kchunks)
            fetch_tiles64<ASRC, BW>((c + 1) * 64, rowBase, colBase,
                                    Af16, lda, Aa, Ab, nt, Bw, ldb, aA, aB);
        __syncthreads();
    }
}

#define FROW(wm16, lane, h) ((wm16) + ((lane) >> 2) + ((h) ? 8 : 0))
#define FCOL(nc, nt2, lane) ((nc) + (nt2) * 8 + ((lane) & 3) * 2)

// ---------------- phase workers ---------------------------------------------

__device__ void do_x(int job, const float* stoc_in, const float* act_t,
                     const float* nt, const float* bi, unsigned char* raw)
{
    __half (*sA)[72] = (__half(*)[72])raw;
    __half (*sB)[72] = (__half(*)[72])(raw + 64 * 72 * 2);
    int rowBase = (job >> 3) * 64, colBase = (job & 7) * 64;
    float c[16];
    gemm_core64<64, SRC_INPUT>(2, nullptr, 0, stoc_in, act_t, nt,
                               g_Wi16, 128, rowBase, colBase, sA, sB, c);
    int lane = threadIdx.x & 31, w = threadIdx.x >> 5;
    int wm16 = (w & 3) * 16, nc = (w >> 2) * 32;
#pragma unroll
    for (int nt2 = 0; nt2 < 4; nt2++) {
        int col = colBase + FCOL(nc, nt2, lane);
#pragma unroll
        for (int h = 0; h < 2; h++) {
            int b = rowBase + FROW(wm16, lane, h);
            float v0 = eluf(c[nt2 * 4 + h * 2]     + bi[col]);
            float v1 = eluf(c[nt2 * 4 + h * 2 + 1] + bi[col + 1]);
            *(__half2*)(g_x16 + (size_t)b * 512 + col) = __floats2half2_rn(v0, v1);
        }
    }
}

__device__ void do_gru(int job, const float* deter_in, const float* nt,
                       const float* b_ih, const float* b_hh,
                       float* deter_out, float* out_t, unsigned char* raw)
{
    __half (*sAx)[40] = (__half(*)[40])(raw);
    __half (*sAh)[40] = (__half(*)[40])(raw + 5120);
    __half (*sBi)[40] = (__half(*)[40])(raw + 10240);
    __half (*sBh)[40] = (__half(*)[40])(raw + 10240 + 15360);

    const int tid = threadIdx.x, lane = tid & 31, w = tid >> 5;
    const int wm16 = (w & 3) * 16, wn = w >> 2;
    const int rowBase = (job >> 3) * 64;
    const int cb192 = (job & 7) * 192;
    const int jb64  = (job & 7) * 64;

    float cgi[48], cgh[48];
#pragma unroll
    for (int i = 0; i < 48; i++) { cgi[i] = 0.f; cgh[i] = 0.f; }

    const __half* Bih = g_Wg16;
    const __half* Bhh = g_Wg16 + 1536 * 512;

    for (int c = 0; c < 16; c++) {
        int k0 = c * 32;
#pragma unroll
        for (int i = 0; i < 4; i++) {
            int ww = tid + i * 256;
            int row = ww >> 4, kp = ww & 15;
            int b = rowBase + row, k = k0 + kp * 2;
            *(uint32_t*)&sAx[row][kp * 2] =
                *(const uint32_t*)(g_x16 + (size_t)b * 512 + k);
            float2 f = *(const float2*)(deter_in + (size_t)b * DET + k);
            float s = nt[b];
            __half2 v = __floats2half2_rn(f.x * s, f.y * s);
            *(uint32_t*)&sAh[row][kp * 2] = *(uint32_t*)&v;
        }
#pragma unroll
        for (int i = 0; i < 12; i++) {
            int ww = tid + i * 256;
            int row = ww >> 4, kp = ww & 15;
            int k = k0 + kp * 2;
            *(uint32_t*)&sBi[row][kp * 2] =
                *(const uint32_t*)(Bih + (size_t)(cb192 + row) * 512 + k);
            *(uint32_t*)&sBh[row][kp * 2] =
                *(const uint32_t*)(Bhh + (size_t)(cb192 + row) * 512 + k);
        }
        __syncthreads();
#pragma unroll
        for (int kk = 0; kk < 2; kk++) {
            int kb = kk * 16;
            uint32_t afx[4], afh[4];
            ldm_x4(afx, &sAx[wm16 + (lane & 15)][kb + ((lane >> 4) << 3)]);
            ldm_x4(afh, &sAh[wm16 + (lane & 15)][kb + ((lane >> 4) << 3)]);
#pragma unroll
            for (int nt2 = 0; nt2 < 12; nt2++) {
                uint32_t bf[2];
                ldm_x2(bf, &sBi[wn * 96 + nt2 * 8 + (lane & 7)][kb + (((lane >> 3) & 1) << 3)]);
                mma16816(cgi + nt2 * 4, afx, bf);
                ldm_x2(bf, &sBh[wn * 96 + nt2 * 8 + (lane & 7)][kb + (((lane >> 3) & 1) << 3)]);
                mma16816(cgh + nt2 * 4, afh, bf);
            }
        }
        __syncthreads();
    }

    float (*rS)[65] = (float(*)[65])(raw);
    float (*zS)[65] = (float(*)[65])(raw + 64 * 65 * 4);

#pragma unroll
    for (int nt2 = 0; nt2 < 12; nt2++) {
#pragma unroll
        for (int h = 0; h < 2; h++) {
            int row = FROW(wm16, lane, h);
#pragma unroll
            for (int q = 0; q < 2; q++) {
                int col = wn * 96 + nt2 * 8 + (lane & 3) * 2 + q;
                int gate = col >> 6, jj = col & 63;
                int j = jb64 + jj;
                float gi = cgi[nt2 * 4 + h * 2 + q];
                float gh = cgh[nt2 * 4 + h * 2 + q];
                if (gate == 0)
                    rS[row][jj] = sigm(gi + gh + b_ih[j] + b_hh[j]);
                else if (gate == 1)
                    zS[row][jj] = sigm(gi + gh + b_ih[512 + j] + b_hh[512 + j]);
            }
        }
    }
    __syncthreads();
#pragma unroll
    for (int nt2 = 0; nt2 < 12; nt2++) {
#pragma unroll
        for (int h = 0; h < 2; h++) {
            int row = FROW(wm16, lane, h);
            int b = rowBase + row;
#pragma unroll
            for (int q = 0; q < 2; q++) {
                int col = wn * 96 + nt2 * 8 + (lane & 3) * 2 + q;
                int gate = col >> 6, jj = col & 63;
                if (gate == 2) {
                    int j = jb64 + jj;
                    float inn = cgi[nt2 * 4 + h * 2 + q] + b_ih[1024 + j];
                    float hn  = cgh[nt2 * 4 + h * 2 + q] + b_hh[1024 + j];
                    float r = rS[row][jj];
                    float z = zS[row][jj];
                    float n = tanhf(inn + r * hn);
                    float hv = deter_in[(size_t)b * DET + j] * nt[b];
                    float dn = (1.f - z) * n + z * hv;
                    deter_out[(size_t)b * DET + j] = dn;
                    g_det16[(size_t)b * 512 + j] = __float2half(dn);
                    out_t[(size_t)b * COUT + j] = dn;
                }
            }
        }
    }
    __syncthreads();
}

__device__ void do_mid(int z, int job, const float* emb_t,
                       const float* bp1, const float* bq1, unsigned char* raw)
{
    __half (*sA)[72] = (__half(*)[72])raw;
    __half (*sB)[72] = (__half(*)[72])(raw + 64 * 72 * 2);
    int rowBase = (job >> 3) * 64, colBase = (job & 7) * 64;
    float c[16];
    if (z)
        gemm_core64<64, SRC_CONCAT>(24, g_det16, 512, emb_t, nullptr, nullptr,
                                    g_Wq116, 1536, rowBase, colBase, sA, sB, c);
    else
        gemm_core64<64, SRC_F16>(8, g_det16, 512, nullptr, nullptr, nullptr,
                                 g_Wp116, 512, rowBase, colBase, sA, sB, c);
    const float* bia = z ? bq1 : bp1;
    __half* outp = z ? g_q116 : g_p116;
    int lane = threadIdx.x & 31, w = threadIdx.x >> 5;
    int wm16 = (w & 3) * 16, nc = (w >> 2) * 32;
#pragma unroll
    for (int nt2 = 0; nt2 < 4; nt2++) {
        int col = colBase + FCOL(nc, nt2, lane);
#pragma unroll
        for (int h = 0; h < 2; h++) {
            int b = rowBase + FROW(wm16, lane, h);
            float v0 = eluf(c[nt2 * 4 + h * 2]     + bia[col]);
            float v1 = eluf(c[nt2 * 4 + h * 2 + 1] + bia[col + 1]);
            *(__half2*)(outp + (size_t)b * 512 + col) = __floats2half2_rn(v0, v1);
        }
    }
}

__device__ void do_head(int z, int rowBlock, const float* b2, const float* eps,
                        float* out_t, float* stoc_out, unsigned char* raw)
{
    __half (*sA)[72] = (__half(*)[72])(raw);
    __half (*sB)[72] = (__half(*)[72])(raw + 64 * 72 * 2);
    int rowBase = rowBlock * 64;
    float c[32];
    if (z)
        gemm_core64<128, SRC_F16>(8, g_q116, 512, nullptr, nullptr, nullptr,
                                  g_Wq216, 512, rowBase, 0, sA, sB, c);
    else
        gemm_core64<128, SRC_F16>(8, g_p116, 512, nullptr, nullptr, nullptr,
                                  g_Wp216, 512, rowBase, 0, sA, sB, c);
    const int obase = z ? (DET + 3 * STO) : DET;
    int lane = threadIdx.x & 31, w = threadIdx.x >> 5;
    int wm16 = (w & 3) * 16, wn = w >> 2;

    float (*Ss)[65] = (float(*)[65])(raw);
    __syncthreads();

    if (wn == 1) {
#pragma unroll
        for (int nt2 = 0; nt2 < 8; nt2++) {
#pragma unroll
            for (int h = 0; h < 2; h++) {
                int row = FROW(wm16, lane, h);
                int b = rowBase + row;
#pragma unroll
                for (int q = 0; q < 2; q++) {
                    int col = 64 + nt2 * 8 + (lane & 3) * 2 + q;
                    int ii = col - 64;
                    float s = softp(c[nt2 * 4 + h * 2 + q] + b2[col]) + 0.1f;
                    Ss[row][ii] = s;
                    out_t[(size_t)b * COUT + obase + STO + ii] = s;
                }
            }
        }
    }
    __syncthreads();
    if (wn == 0) {
#pragma unroll
        for (int nt2 = 0; nt2 < 8; nt2++) {
#pragma unroll
            for (int h = 0; h < 2; h++) {
                int row = FROW(wm16, lane, h);
                int b = rowBase + row;
#pragma unroll
                for (int q = 0; q < 2; q++) {
                    int ii = nt2 * 8 + (lane & 3) * 2 + q;
                    float m = c[nt2 * 4 + h * 2 + q] + b2[ii];
                    float s = Ss[row][ii];
                    float st = m + s * eps[b * STO + ii];
                    size_t base = (size_t)b * COUT + obase;
                    out_t[base + ii]           = m;
                    out_t[base + 2 * STO + ii] = st;
                    if (z) stoc_out[b * STO + ii] = st;
                }
            }
        }
    }
    __syncthreads();
}

// ---------------- the persistent kernel --------------------------------------
__global__ __launch_bounds__(256, 1) void k_rssm(
    const float* __restrict__ actions, const float* __restrict__ nonterm,
    const float* __restrict__ emb, const float* __restrict__ init_deter,
    const float* __restrict__ init_stoc, const float* __restrict__ noise_p,
    const float* __restrict__ noise_q,
    const float* __restrict__ Wi,   const float* __restrict__ bi,
    const float* __restrict__ W_ih, const float* __restrict__ W_hh,
    const float* __restrict__ b_ih, const float* __restrict__ b_hh,
    const float* __restrict__ Wp1,  const float* __restrict__ bp1,
    const float* __restrict__ Wp2,  const float* __restrict__ bp2,
    const float* __restrict__ Wq1,  const float* __restrict__ bq1,
    const float* __restrict__ Wq2,  const float* __restrict__ bq2,
    float* __restrict__ out)
{
    __shared__ __align__(16) unsigned char raw[40960];
    const int bid = blockIdx.x;
    unsigned bar_t = 0;
    if (threadIdx.x == 0) bar_t = g_barsense;

    // ---- phase 0: weight prep ----
    {
        const int gt = bid * 256 + threadIdx.x;
        const int NTH = NCTA * 256;
        for (int i = gt; i < 512 * 128; i += NTH) {
            int n = i >> 7, k = i & 127;
            g_Wi16[i] = __float2half(k < 70 ? Wi[(size_t)k * 512 + n] : 0.f);
        }
        for (int i = gt; i < 1536 * 512; i += NTH) {
            int rr = i >> 9, k = i & 511;
            int jb = rr / 192, rem = rr % 192;
            int gate = rem >> 6, jj = rem & 63;
            int srow = gate * 512 + jb * 64 + jj;
            g_Wg16[i]              = __float2half(W_ih[(size_t)srow * 512 + k]);
            g_Wg16[1536 * 512 + i] = __float2half(W_hh[(size_t)srow * 512 + k]);
        }
        for (int i = gt; i < 512 * 512; i += NTH) {
            int n = i >> 9, k = i & 511;
            g_Wp116[i] = __float2half(Wp1[(size_t)k * 512 + n]);
        }
        for (int i = gt; i < 512 * 1536; i += NTH) {
            int n = i / 1536, k = i - n * 1536;
            g_Wq116[i] = __float2half(Wq1[(size_t)k * 512 + n]);
        }
        for (int i = gt; i < 128 * 512; i += NTH) {
            int n = i >> 9, k = i & 511;
            g_Wp216[i] = __float2half(Wp2[(size_t)k * 128 + n]);
            g_Wq216[i] = __float2half(Wq2[(size_t)k * 128 + n]);
        }
    }
    grid_bar(bar_t);

    for (int t = 0; t < TT; t++) {
        const float* stoc_in  = t ? g_stoc  + ((t + 1) & 1) * BBATCH * STO : init_stoc;
        const float* deter_in = t ? g_deter + ((t + 1) & 1) * BBATCH * DET : init_deter;
        float* deter_out = g_deter + (t & 1) * BBATCH * DET;
        float* stoc_out  = g_stoc  + (t & 1) * BBATCH * STO;
        const float* nt_t  = nonterm + (size_t)t * BBATCH;
        const float* act_t = actions + (size_t)t * BBATCH * ACTD;
        const float* emb_t = emb     + (size_t)t * BBATCH * EMBD;
        float* out_t = out + (size_t)t * BBATCH * COUT;

        // phase A: input GEMM (128 jobs)
        if (bid < 128) do_x(bid, stoc_in, act_t, nt_t, bi, raw);
        grid_bar(bar_t);

        // phase B: fused GRU (128 jobs) || deferred prior head of t-1 (16 jobs)
        if (bid < 128)
            do_gru(bid, deter_in, nt_t, b_ih, b_hh, deter_out, out_t, raw);
        else if (bid < 144 && t > 0)
            do_head(0, bid - 128, bp2,
                    noise_p + (size_t)(t - 1) * BBATCH * STO,
                    out + (size_t)(t - 1) * BBATCH * COUT, nullptr, raw);
        grid_bar(bar_t);

        // phase C: mid layers (128 q1-heavy + 128 p1)
        for (int j = bid; j < 256; j += NCTA)
            do_mid(j < 128 ? 1 : 0, j & 127, emb_t, bp1, bq1, raw);
        grid_bar(bar_t);

        // phase D: posterior head (16 jobs) — gates the recurrence
        if (bid < 16)
            do_head(1, bid, bq2, noise_q + (size_t)t * BBATCH * STO,
                    out_t, stoc_out, raw);
        grid_bar(bar_t);
    }

    // final deferred prior head for t = TT-1
    if (bid < 16)
        do_head(0, bid, bp2, noise_p + (size_t)(TT - 1) * BBATCH * STO,
                out + (size_t)(TT - 1) * BBATCH * COUT, nullptr, raw);
}

// ---------------------------------------------------------------------------
extern "C" void kernel_launch(void* const* d_in, const int* in_sizes, int n_in,
                              void* d_out, int out_size)
{
    const float* actions    = (const float*)d_in[0];
    const float* nonterm    = (const float*)d_in[1];
    const float* emb        = (const float*)d_in[2];
    const float* init_deter = (const float*)d_in[3];
    const float* init_stoc  = (const float*)d_in[4];
    const float* noise_p    = (const float*)d_in[5];
    const float* noise_q    = (const float*)d_in[6];
    const float* Wi   = (const float*)d_in[7];
    const float* bi   = (const float*)d_in[8];
    const float* W_ih = (const float*)d_in[9];
    const float* W_hh = (const float*)d_in[10];
    const float* b_ih = (const float*)d_in[11];
    const float* b_hh = (const float*)d_in[12];
    const float* Wp1  = (const float*)d_in[13];
    const float* bp1  = (const float*)d_in[14];
    const float* Wp2  = (const float*)d_in[15];
    const float* bp2  = (const float*)d_in[16];
    const float* Wq1  = (const float*)d_in[17];
    const float* bq1  = (const float*)d_in[18];
    const float* Wq2  = (const float*)d_in[19];
    const float* bq2  = (const float*)d_in[20];
    float* out = (float*)d_out;

    k_rssm<<<NCTA, 256>>>(actions, nonterm, emb, init_deter, init_stoc,
                          noise_p, noise_q, Wi, bi, W_ih, W_hh, b_ih, b_hh,
                          Wp1, bp1, Wp2, bp2, Wq1, bq1, Wq2, bq2, out);
}

// round 11
// speedup vs baseline: 1.0133x; 1.0133x over previous
#include <cuda_runtime.h>
#include <cuda_fp16.h>
#include <math.h>
#include <stdint.h>

#define TT     64
#define BBATCH 1024
#define DET    512
#define STO    64
#define EMBD   1024
#define ACTD   6
#define MLPD   512
#define COUT   896

// ---------------- persistent scratch ----------------------------------------
__device__ __align__(16) __half g_Wi16 [512 * 128];
__device__ __align__(16) __half g_Wg16 [2 * 1536 * 512];   // gate-interleaved W_ih|W_hh
__device__ __align__(16) __half g_Wp116[512 * 512];
__device__ __align__(16) __half g_Wq116[512 * 1536];
__device__ __align__(16) __half g_Wp216[128 * 512];
__device__ __align__(16) __half g_Wq216[128 * 512];
__device__ __align__(16) __half g_x16  [BBATCH * 512];
__device__ __align__(16) __half g_det16[BBATCH * 512];
__device__ __align__(16) __half g_p116 [BBATCH * 512];
__device__ __align__(16) __half g_q116 [BBATCH * 512];
__device__ __align__(16) float  g_deter[2 * BBATCH * 512];
__device__ __align__(16) float  g_stoc [2 * BBATCH * 64];

// ---------------- math ------------------------------------------------------
__device__ __forceinline__ float eluf(float x)  { return x > 0.f ? x : expm1f(x); }
__device__ __forceinline__ float sigm(float x)  { return 1.f / (1.f + expf(-x)); }
__device__ __forceinline__ float softp(float x) { return x > 0.f ? x + log1pf(expf(-x)) : log1pf(expf(x)); }

// ---------------- MMA primitives --------------------------------------------
__device__ __forceinline__ void ldm_x4(uint32_t* r, const void* p) {
    uint32_t a;
    asm("{ .reg .u64 t; cvta.to.shared.u64 t, %1; cvt.u32.u64 %0, t; }" : "=r"(a) : "l"(p));
    asm volatile("ldmatrix.sync.aligned.m8n8.x4.shared.b16 {%0,%1,%2,%3}, [%4];"
                 : "=r"(r[0]), "=r"(r[1]), "=r"(r[2]), "=r"(r[3]) : "r"(a));
}
__device__ __forceinline__ void ldm_x2(uint32_t* r, const void* p) {
    uint32_t a;
    asm("{ .reg .u64 t; cvta.to.shared.u64 t, %1; cvt.u32.u64 %0, t; }" : "=r"(a) : "l"(p));
    asm volatile("ldmatrix.sync.aligned.m8n8.x2.shared.b16 {%0,%1}, [%2];"
                 : "=r"(r[0]), "=r"(r[1]) : "r"(a));
}
__device__ __forceinline__ void mma16816(float* c, const uint32_t* a, const uint32_t* b) {
    asm volatile(
        "mma.sync.aligned.m16n8k16.row.col.f32.f16.f16.f32 "
        "{%0,%1,%2,%3}, {%4,%5,%6,%7}, {%8,%9}, {%0,%1,%2,%3};"
        : "+f"(c[0]), "+f"(c[1]), "+f"(c[2]), "+f"(c[3])
        : "r"(a[0]), "r"(a[1]), "r"(a[2]), "r"(a[3]), "r"(b[0]), "r"(b[1]));
}

// ---------------- A-tile sources --------------------------------------------
#define SRC_F16    0
#define SRC_INPUT  2
#define SRC_CONCAT 3

template<int ASRC, int BW>
__device__ __forceinline__ void fetch_tiles64(
    int k0, int rowBase, int colBase,
    const __half* Af16, int lda,
    const float* Aa, const float* Ab, const float* nt,
    const __half* Bw, int ldb,
    uint32_t* aA, uint32_t* aB)
{
    const int tid = threadIdx.x;
#pragma unroll
    for (int i = 0; i < 8; i++) {
        int w = tid + i * 256;
        int row = w >> 5, kp = w & 31;
        int b = rowBase + row;
        int k = k0 + kp * 2;
        __half2 v;
        if (ASRC == SRC_F16) {
            v = *(const __half2*)(Af16 + (size_t)b * lda + k);
        } else if (ASRC == SRC_CONCAT) {
            if (k < DET) {
                v = *(const __half2*)(Af16 + (size_t)b * DET + k);
            } else {
                float2 f = *(const float2*)(Aa + (size_t)b * EMBD + (k - DET));
                v = __floats2half2_rn(f.x, f.y);
            }
        } else { // SRC_INPUT
            float s = nt[b];
            float lo = (k < STO) ? Aa[b * STO + k] * s
                     : ((k < STO + ACTD) ? Ab[b * ACTD + (k - STO)] : 0.f);
            int k1 = k + 1;
            float hi = (k1 < STO) ? Aa[b * STO + k1] * s
                     : ((k1 < STO + ACTD) ? Ab[b * ACTD + (k1 - STO)] : 0.f);
            v = __floats2half2_rn(lo, hi);
        }
        aA[i] = *(uint32_t*)&v;
    }
#pragma unroll
    for (int i = 0; i < BW; i++) {
        int w = tid + i * 256;
        int row = w >> 5, kp = w & 31;
        __half2 v = *(const __half2*)(Bw + (size_t)(colBase + row) * ldb + k0 + kp * 2);
        aB[i] = *(uint32_t*)&v;
    }
}

// ---- C[64 x NCOLS] = A[64xK] * B[NCOLS x K]^T, double-buffered -------------
template<int NCOLS, int ASRC>
__device__ __forceinline__ void gemm_core64(
    int kchunks,
    const __half* Af16, int lda,
    const float* Aa, const float* Ab, const float* nt,
    const __half* Bw, int ldb,
    int rowBase, int colBase,
    unsigned char* raw,
    float* cacc)
{
    constexpr int BW = NCOLS / 8;
    constexpr int NT = NCOLS / 16;
    constexpr int STAGE = 64 * 72 * 2 + NCOLS * 72 * 2;
    const int tid = threadIdx.x, lane = tid & 31, w = tid >> 5;
    const int mrow = (w & 3) * 16;
    const int ncol = (w >> 2) * (NCOLS / 2);

#pragma unroll
    for (int i = 0; i < NT * 4; i++) cacc[i] = 0.f;

    uint32_t aA[8], aB[BW];
    fetch_tiles64<ASRC, BW>(0, rowBase, colBase, Af16, lda, Aa, Ab, nt, Bw, ldb, aA, aB);

    for (int c = 0; c < kchunks; c++) {
        unsigned char* base = raw + (c & 1) * STAGE;
        __half (*sA)[72] = (__half(*)[72])base;
        __half (*sB)[72] = (__half(*)[72])(base + 64 * 72 * 2);
#pragma unroll
        for (int i = 0; i < 8; i++) {
            int ww = tid + i * 256;
            *(uint32_t*)&sA[ww >> 5][(ww & 31) * 2] = aA[i];
        }
#pragma unroll
        for (int i = 0; i < BW; i++) {
            int ww = tid + i * 256;
            *(uint32_t*)&sB[ww >> 5][(ww & 31) * 2] = aB[i];
        }
        __syncthreads();
        if (c + 1 < kchunks)
            fetch_tiles64<ASRC, BW>((c + 1) * 64, rowBase, colBase,
                                    Af16, lda, Aa, Ab, nt, Bw, ldb, aA, aB);
#pragma unroll
        for (int kk = 0; kk < 4; kk++) {
            int kb = kk * 16;
            uint32_t afr[4];
            ldm_x4(afr, &sA[mrow + (lane & 15)][kb + ((lane >> 4) << 3)]);
            uint32_t bfr[NT][2];
#pragma unroll
            for (int nt2 = 0; nt2 < NT; nt2++)
                ldm_x2(bfr[nt2], &sB[ncol + nt2 * 8 + (lane & 7)][kb + (((lane >> 3) & 1) << 3)]);
#pragma unroll
            for (int nt2 = 0; nt2 < NT; nt2++)
                mma16816(cacc + nt2 * 4, afr, bfr[nt2]);
        }
    }
    __syncthreads();
}

#define FROW(wm16, lane, h) ((wm16) + ((lane) >> 2) + ((h) ? 8 : 0))
#define FCOL(nc, nt2, lane) ((nc) + (nt2) * 8 + ((lane) & 3) * 2)

// ---------------- head worker (z=0 prior, z=1 posterior) ---------------------
__device__ void do_head(int z, int rowBlock, const float* b2, const float* eps,
                        float* out_t, float* stoc_out, unsigned char* raw)
{
    int rowBase = rowBlock * 64;
    float c[32];
    if (z)
        gemm_core64<128, SRC_F16>(8, g_q116, 512, nullptr, nullptr, nullptr,
                                  g_Wq216, 512, rowBase, 0, raw, c);
    else
        gemm_core64<128, SRC_F16>(8, g_p116, 512, nullptr, nullptr, nullptr,
                                  g_Wp216, 512, rowBase, 0, raw, c);
    const int obase = z ? (DET + 3 * STO) : DET;
    int lane = threadIdx.x & 31, w = threadIdx.x >> 5;
    int wm16 = (w & 3) * 16, wn = w >> 2;

    float (*Ss)[65] = (float(*)[65])(raw);

    if (wn == 1) {
#pragma unroll
        for (int nt2 = 0; nt2 < 8; nt2++) {
#pragma unroll
            for (int h = 0; h < 2; h++) {
                int row = FROW(wm16, lane, h);
                int b = rowBase + row;
#pragma unroll
                for (int q = 0; q < 2; q++) {
                    int col = 64 + nt2 * 8 + (lane & 3) * 2 + q;
                    int ii = col - 64;
                    float s = softp(c[nt2 * 4 + h * 2 + q] + b2[col]) + 0.1f;
                    Ss[row][ii] = s;
                    out_t[(size_t)b * COUT + obase + STO + ii] = s;
                }
            }
        }
    }
    __syncthreads();
    if (wn == 0) {
#pragma unroll
        for (int nt2 = 0; nt2 < 8; nt2++) {
#pragma unroll
            for (int h = 0; h < 2; h++) {
                int row = FROW(wm16, lane, h);
                int b = rowBase + row;
#pragma unroll
                for (int q = 0; q < 2; q++) {
                    int ii = nt2 * 8 + (lane & 3) * 2 + q;
                    float m = c[nt2 * 4 + h * 2 + q] + b2[ii];
                    float s = Ss[row][ii];
                    float st = m + s * eps[b * STO + ii];
                    size_t base = (size_t)b * COUT + obase;
                    out_t[base + ii]           = m;
                    out_t[base + 2 * STO + ii] = st;
                    if (z) stoc_out[b * STO + ii] = st;
                }
            }
        }
    }
}

// ---------------- prep kernels ----------------------------------------------
__global__ __launch_bounds__(256) void k_prep(
    const float* __restrict__ src, __half* __restrict__ dst,
    int total, int srcK, int dstK, int srcN, int trans)
{
    for (int idx = blockIdx.x * 256 + threadIdx.x; idx < total; idx += gridDim.x * 256) {
        int n = idx / dstK, k = idx % dstK;
        float v = 0.f;
        if (k < srcK)
            v = trans ? src[(size_t)k * srcN + n] : src[(size_t)n * srcK + k];
        dst[idx] = __float2half(v);
    }
}

__global__ __launch_bounds__(256) void k_prep_gru(
    const float* __restrict__ Wih, const float* __restrict__ Whh,
    __half* __restrict__ dst)
{
    int total = 1536 * 512;
    for (int idx = blockIdx.x * 256 + threadIdx.x; idx < total; idx += gridDim.x * 256) {
        int rr = idx / 512, k = idx % 512;
        int jb = rr / 192, rem = rr % 192;
        int gate = rem >> 6, jj = rem & 63;
        int srow = gate * 512 + jb * 64 + jj;
        dst[idx]         = __float2half(Wih[(size_t)srow * 512 + k]);
        dst[total + idx] = __float2half(Whh[(size_t)srow * 512 + k]);
    }
}

// ---------------- step kernels ----------------------------------------------

// K1: x GEMM (blocks 0..127) + deferred prior head of step t-1 (blocks 128..143)
__global__ __launch_bounds__(256) void kg_xh(
    const float* __restrict__ stoc_in, const float* __restrict__ act_t,
    const float* __restrict__ nt, const float* __restrict__ bi,
    const float* __restrict__ bp2, const float* __restrict__ eps_pm1,
    float* __restrict__ out_tm1, int do_prior)
{
    extern __shared__ __align__(16) unsigned char raw[];
    int bid = blockIdx.x;
    if (bid < 128) {
        int rowBase = (bid >> 3) * 64, colBase = (bid & 7) * 64;
        float c[16];
        gemm_core64<64, SRC_INPUT>(2, nullptr, 0, stoc_in, act_t, nt,
                                   g_Wi16, 128, rowBase, colBase, raw, c);
        int lane = threadIdx.x & 31, w = threadIdx.x >> 5;
        int wm16 = (w & 3) * 16, nc = (w >> 2) * 32;
#pragma unroll
        for (int nt2 = 0; nt2 < 4; nt2++) {
            int col = colBase + FCOL(nc, nt2, lane);
#pragma unroll
            for (int h = 0; h < 2; h++) {
                int b = rowBase + FROW(wm16, lane, h);
                float v0 = eluf(c[nt2 * 4 + h * 2]     + bi[col]);
                float v1 = eluf(c[nt2 * 4 + h * 2 + 1] + bi[col + 1]);
                *(__half2*)(g_x16 + (size_t)b * 512 + col) = __floats2half2_rn(v0, v1);
            }
        }
    } else if (do_prior) {
        do_head(0, bid - 128, bp2, eps_pm1, out_tm1, nullptr, raw);
    }
}

// K2: fused GRU, double-buffered.  grid(8,16), dyn smem 81920.
__global__ __launch_bounds__(256) void kg_gruf(
    const float* __restrict__ deter_in, const float* __restrict__ nt,
    const float* __restrict__ b_ih, const float* __restrict__ b_hh,
    float* __restrict__ deter_out, float* __restrict__ out_t)
{
    extern __shared__ __align__(16) unsigned char raw[];
    const int tid = threadIdx.x, lane = tid & 31, w = tid >> 5;
    const int wm16 = (w & 3) * 16, wn = w >> 2;
    const int rowBase = blockIdx.y * 64;
    const int cb192 = blockIdx.x * 192;
    const int jb64  = blockIdx.x * 64;

    float cgi[48], cgh[48];
#pragma unroll
    for (int i = 0; i < 48; i++) { cgi[i] = 0.f; cgh[i] = 0.f; }

    const __half* Bih = g_Wg16;
    const __half* Bhh = g_Wg16 + 1536 * 512;

    uint32_t pAx[4], pAh[4], pBi[12], pBh[12];
#define GRU_FETCH(cc) do { \
        int k0 = (cc) * 32; \
        _Pragma("unroll") \
        for (int i = 0; i < 4; i++) { \
            int ww = tid + i * 256; \
            int row = ww >> 4, kp = ww & 15; \
            int b = rowBase + row, k = k0 + kp * 2; \
            pAx[i] = *(const uint32_t*)(g_x16 + (size_t)b * 512 + k); \
            float2 f = *(const float2*)(deter_in + (size_t)b * DET + k); \
            float s = nt[b]; \
            __half2 v = __floats2half2_rn(f.x * s, f.y * s); \
            pAh[i] = *(uint32_t*)&v; \
        } \
        _Pragma("unroll") \
        for (int i = 0; i < 12; i++) { \
            int ww = tid + i * 256; \
            int row = ww >> 4, kp = ww & 15; \
            int k = k0 + kp * 2; \
            pBi[i] = *(const uint32_t*)(Bih + (size_t)(cb192 + row) * 512 + k); \
            pBh[i] = *(const uint32_t*)(Bhh + (size_t)(cb192 + row) * 512 + k); \
        } \
    } while (0)

    GRU_FETCH(0);
    for (int c = 0; c < 16; c++) {
        unsigned char* base = raw + (c & 1) * 40960;
        __half (*sAx)[40] = (__half(*)[40])(base);
        __half (*sAh)[40] = (__half(*)[40])(base + 5120);
        __half (*sBi)[40] = (__half(*)[40])(base + 10240);
        __half (*sBh)[40] = (__half(*)[40])(base + 25600);
#pragma unroll
        for (int i = 0; i < 4; i++) {
            int ww = tid + i * 256;
            int row = ww >> 4, kp = ww & 15;
            *(uint32_t*)&sAx[row][kp * 2] = pAx[i];
            *(uint32_t*)&sAh[row][kp * 2] = pAh[i];
        }
#pragma unroll
        for (int i = 0; i < 12; i++) {
            int ww = tid + i * 256;
            int row = ww >> 4, kp = ww & 15;
            *(uint32_t*)&sBi[row][kp * 2] = pBi[i];
            *(uint32_t*)&sBh[row][kp * 2] = pBh[i];
        }
        __syncthreads();
        if (c + 1 < 16) GRU_FETCH(c + 1);
#pragma unroll
        for (int kk = 0; kk < 2; kk++) {
            int kb = kk * 16;
            uint32_t afx[4], afh[4];
            ldm_x4(afx, &sAx[wm16 + (lane & 15)][kb + ((lane >> 4) << 3)]);
            ldm_x4(afh, &sAh[wm16 + (lane & 15)][kb + ((lane >> 4) << 3)]);
#pragma unroll
            for (int nt2 = 0; nt2 < 12; nt2++) {
                uint32_t bf[2];
                ldm_x2(bf, &sBi[wn * 96 + nt2 * 8 + (lane & 7)][kb + (((lane >> 3) & 1) << 3)]);
                mma16816(cgi + nt2 * 4, afx, bf);
                ldm_x2(bf, &sBh[wn * 96 + nt2 * 8 + (lane & 7)][kb + (((lane >> 3) & 1) << 3)]);
                mma16816(cgh + nt2 * 4, afh, bf);
            }
        }
        __syncthreads();
    }

    float (*rS)[65] = (float(*)[65])(raw);
    float (*zS)[65] = (float(*)[65])(raw + 64 * 65 * 4);

#pragma unroll
    for (int nt2 = 0; nt2 < 12; nt2++) {
#pragma unroll
        for (int h = 0; h < 2; h++) {
            int row = FROW(wm16, lane, h);
#pragma unroll
            for (int q = 0; q < 2; q++) {
                int col = wn * 96 + nt2 * 8 + (lane & 3) * 2 + q;
                int gate = col >> 6, jj = col & 63;
                int j = jb64 + jj;
                float gi = cgi[nt2 * 4 + h * 2 + q];
                float gh = cgh[nt2 * 4 + h * 2 + q];
                if (gate == 0)
                    rS[row][jj] = sigm(gi + gh + b_ih[j] + b_hh[j]);
                else if (gate == 1)
                    zS[row][jj] = sigm(gi + gh + b_ih[512 + j] + b_hh[512 + j]);
            }
        }
    }
    __syncthreads();
#pragma unroll
    for (int nt2 = 0; nt2 < 12; nt2++) {
#pragma unroll
        for (int h = 0; h < 2; h++) {
            int row = FROW(wm16, lane, h);
            int b = rowBase + row;
#pragma unroll
            for (int q = 0; q < 2; q++) {
                int col = wn * 96 + nt2 * 8 + (lane & 3) * 2 + q;
                int gate = col >> 6, jj = col & 63;
                if (gate == 2) {
                    int j = jb64 + jj;
                    float inn = cgi[nt2 * 4 + h * 2 + q] + b_ih[1024 + j];
                    float hn  = cgh[nt2 * 4 + h * 2 + q] + b_hh[1024 + j];
                    float r = rS[row][jj];
                    float z = zS[row][jj];
                    float n = tanhf(inn + r * hn);
                    float hv = deter_in[(size_t)b * DET + j] * nt[b];
                    float dn = (1.f - z) * n + z * hv;
                    deter_out[(size_t)b * DET + j] = dn;
                    g_det16[(size_t)b * 512 + j] = __float2half(dn);
                    out_t[(size_t)b * COUT + j] = dn;
                }
            }
        }
    }
}

// K3: p1 (z=0, K=512) / q1 (z=1, K=1536)   grid(8,16,2), dyn smem 36864
__global__ __launch_bounds__(256) void kg_mid(
    const float* __restrict__ emb_t,
    const float* __restrict__ bp1, const float* __restrict__ bq1)
{
    extern __shared__ __align__(16) unsigned char raw[];
    int z = blockIdx.z;
    int rowBase = blockIdx.y * 64, colBase = blockIdx.x * 64;
    float c[16];
    if (z)
        gemm_core64<64, SRC_CONCAT>(24, g_det16, 512, emb_t, nullptr, nullptr,
                                    g_Wq116, 1536, rowBase, colBase, raw, c);
    else
        gemm_core64<64, SRC_F16>(8, g_det16, 512, nullptr, nullptr, nullptr,
                                 g_Wp116, 512, rowBase, colBase, raw, c);
    const float* bia = z ? bq1 : bp1;
    __half* outp = z ? g_q116 : g_p116;
    int lane = threadIdx.x & 31, w = threadIdx.x >> 5;
    int wm16 = (w & 3) * 16, nc = (w >> 2) * 32;
#pragma unroll
    for (int nt2 = 0; nt2 < 4; nt2++) {
        int col = colBase + FCOL(nc, nt2, lane);
#pragma unroll
        for (int h = 0; h < 2; h++) {
            int b = rowBase + FROW(wm16, lane, h);
            float v0 = eluf(c[nt2 * 4 + h * 2]     + bia[col]);
            float v1 = eluf(c[nt2 * 4 + h * 2 + 1] + bia[col + 1]);
            *(__half2*)(outp + (size_t)b * 512 + col) = __floats2half2_rn(v0, v1);
        }
    }
}

// K4: head (z selectable)   grid(16), dyn smem 55296
__global__ __launch_bounds__(256) void kg_head(
    int z, const float* __restrict__ b2, const float* __restrict__ eps,
    float* __restrict__ out_t, float* __restrict__ stoc_out)
{
    extern __shared__ __align__(16) unsigned char raw[];
    do_head(z, blockIdx.x, b2, eps, out_t, stoc_out, raw);
}

// ---------------------------------------------------------------------------
extern "C" void kernel_launch(void* const* d_in, const int* in_sizes, int n_in,
                              void* d_out, int out_size)
{
    const float* actions    = (const float*)d_in[0];
    const float* nonterm    = (const float*)d_in[1];
    const float* emb        = (const float*)d_in[2];
    const float* init_deter = (const float*)d_in[3];
    const float* init_stoc  = (const float*)d_in[4];
    const float* noise_p    = (const float*)d_in[5];
    const float* noise_q    = (const float*)d_in[6];
    const float* Wi   = (const float*)d_in[7];
    const float* bi   = (const float*)d_in[8];
    const float* W_ih = (const float*)d_in[9];
    const float* W_hh = (const float*)d_in[10];
    const float* b_ih = (const float*)d_in[11];
    const float* b_hh = (const float*)d_in[12];
    const float* Wp1  = (const float*)d_in[13];
    const float* bp1  = (const float*)d_in[14];
    const float* Wp2  = (const float*)d_in[15];
    const float* bp2  = (const float*)d_in[16];
    const float* Wq1  = (const float*)d_in[17];
    const float* bq1  = (const float*)d_in[18];
    const float* Wq2  = (const float*)d_in[19];
    const float* bq2  = (const float*)d_in[20];
    float* out = (float*)d_out;

    __half *wi16, *wg16, *wp116, *wq116, *wp216, *wq216;
    float  *deterBuf, *stocBuf;
    cudaGetSymbolAddress((void**)&wi16,  g_Wi16);
    cudaGetSymbolAddress((void**)&wg16,  g_Wg16);
    cudaGetSymbolAddress((void**)&wp116, g_Wp116);
    cudaGetSymbolAddress((void**)&wq116, g_Wq116);
    cudaGetSymbolAddress((void**)&wp216, g_Wp216);
    cudaGetSymbolAddress((void**)&wq216, g_Wq216);
    cudaGetSymbolAddress((void**)&deterBuf, g_deter);
    cudaGetSymbolAddress((void**)&stocBuf,  g_stoc);

    // idempotent, called every invocation (no static guards allowed)
    cudaFuncSetAttribute(kg_xh,   cudaFuncAttributeMaxDynamicSharedMemorySize, 55296);
    cudaFuncSetAttribute(kg_gruf, cudaFuncAttributeMaxDynamicSharedMemorySize, 81920);
    cudaFuncSetAttribute(kg_head, cudaFuncAttributeMaxDynamicSharedMemorySize, 55296);
    cudaFuncSetAttribute(kg_mid,  cudaFuncAttributeMaxDynamicSharedMemorySize, 36864);

    auto prep = [&](const float* src, __half* dst, int N, int srcK, int dstK, int srcN, int trans) {
        int total = N * dstK;
        k_prep<<<(total + 255) / 256, 256>>>(src, dst, total, srcK, dstK, srcN, trans);
    };
    prep(Wi,  wi16,  512, 70,   128,  512, 1);
    prep(Wp1, wp116, 512, 512,  512,  512, 1);
    prep(Wq1, wq116, 512, 1536, 1536, 512, 1);
    prep(Wp2, wp216, 128, 512,  512,  128, 1);
    prep(Wq2, wq216, 128, 512,  512,  128, 1);
    k_prep_gru<<<1024, 256>>>(W_ih, W_hh, wg16);

    for (int t = 0; t < TT; t++) {
        const float* stoc_in  = t ? stocBuf  + ((t + 1) & 1) * BBATCH * STO : init_stoc;
        const float* deter_in = t ? deterBuf + ((t + 1) & 1) * BBATCH * DET : init_deter;
        float* deter_out = deterBuf + (t & 1) * BBATCH * DET;
        float* stoc_out  = stocBuf  + (t & 1) * BBATCH * STO;
        const float* nt_t  = nonterm + (size_t)t * BBATCH;
        const float* act_t = actions + (size_t)t * BBATCH * ACTD;
        const float* emb_t = emb     + (size_t)t * BBATCH * EMBD;
        float* out_t = out + (size_t)t * BBATCH * COUT;

        kg_xh  <<<144, 256, 55296>>>(stoc_in, act_t, nt_t, bi, bp2,
                                     noise_p + (size_t)(t ? t - 1 : 0) * BBATCH * STO,
                                     out + (size_t)(t ? t - 1 : 0) * BBATCH * COUT,
                                     t > 0 ? 1 : 0);
        kg_gruf<<<dim3(8, 16), 256, 81920>>>(deter_in, nt_t, b_ih, b_hh,
                                             deter_out, out_t);
        kg_mid <<<dim3(8, 16, 2), 256, 36864>>>(emb_t, bp1, bq1);
        kg_head<<<16, 256, 55296>>>(1, bq2,
                                    noise_q + (size_t)t * BBATCH * STO,
                                    out_t, stoc_out);
    }
    // final deferred prior head (t = TT-1)
    kg_head<<<16, 256, 55296>>>(0, bp2,
                                noise_p + (size_t)(TT - 1) * BBATCH * STO,
                                out + (size_t)(TT - 1) * BBATCH * COUT, nullptr);
}

// round 12
// speedup vs baseline: 1.1101x; 1.0955x over previous
#include <cuda_runtime.h>
#include <cuda_fp16.h>
#include <math.h>
#include <stdint.h>

#define TT     64
#define BBATCH 1024
#define DET    512
#define STO    64
#define EMBD   1024
#define ACTD   6
#define MLPD   512
#define COUT   896

// ---------------- persistent scratch ----------------------------------------
__device__ __align__(16) __half g_Wi16 [512 * 128];
__device__ __align__(16) __half g_Wg16 [2 * 1536 * 512];   // gate-interleaved W_ih|W_hh
__device__ __align__(16) __half g_Wp116[512 * 512];
__device__ __align__(16) __half g_Wq116[512 * 1536];
__device__ __align__(16) __half g_Wp216[128 * 512];
__device__ __align__(16) __half g_Wq216[128 * 512];
__device__ __align__(16) __half g_x16  [BBATCH * 512];
__device__ __align__(16) __half g_det16[BBATCH * 512];
__device__ __align__(16) __half g_p116 [BBATCH * 512];
__device__ __align__(16) __half g_q116 [BBATCH * 512];
__device__ __align__(16) float  g_deter[2 * BBATCH * 512];
__device__ __align__(16) float  g_stoc [2 * BBATCH * 64];

// ---------------- math ------------------------------------------------------
__device__ __forceinline__ float eluf(float x)  { return x > 0.f ? x : expm1f(x); }
__device__ __forceinline__ float sigm(float x)  { return 1.f / (1.f + expf(-x)); }
__device__ __forceinline__ float softp(float x) { return x > 0.f ? x + log1pf(expf(-x)) : log1pf(expf(x)); }

// ---------------- MMA primitives --------------------------------------------
__device__ __forceinline__ void ldm_x4(uint32_t* r, const void* p) {
    uint32_t a;
    asm("{ .reg .u64 t; cvta.to.shared.u64 t, %1; cvt.u32.u64 %0, t; }" : "=r"(a) : "l"(p));
    asm volatile("ldmatrix.sync.aligned.m8n8.x4.shared.b16 {%0,%1,%2,%3}, [%4];"
                 : "=r"(r[0]), "=r"(r[1]), "=r"(r[2]), "=r"(r[3]) : "r"(a));
}
__device__ __forceinline__ void ldm_x2(uint32_t* r, const void* p) {
    uint32_t a;
    asm("{ .reg .u64 t; cvta.to.shared.u64 t, %1; cvt.u32.u64 %0, t; }" : "=r"(a) : "l"(p));
    asm volatile("ldmatrix.sync.aligned.m8n8.x2.shared.b16 {%0,%1}, [%2];"
                 : "=r"(r[0]), "=r"(r[1]) : "r"(a));
}
__device__ __forceinline__ void mma16816(float* c, const uint32_t* a, const uint32_t* b) {
    asm volatile(
        "mma.sync.aligned.m16n8k16.row.col.f32.f16.f16.f32 "
        "{%0,%1,%2,%3}, {%4,%5,%6,%7}, {%8,%9}, {%0,%1,%2,%3};"
        : "+f"(c[0]), "+f"(c[1]), "+f"(c[2]), "+f"(c[3])
        : "r"(a[0]), "r"(a[1]), "r"(a[2]), "r"(a[3]), "r"(b[0]), "r"(b[1]));
}

// ---------------- A-tile sources --------------------------------------------
#define SRC_F16    0
#define SRC_INPUT  2
#define SRC_CONCAT 3

// ---- generic C[MROWS x NCOLS] = A[MROWSxK] * B[NCOLS x K]^T ----------------
// 8 warps: WMW m-tiles of 16 rows (WMW=MROWS/16), WNW=8/WMW n-groups.
template<int MROWS, int NCOLS, int ASRC>
__device__ __forceinline__ void gemm_core(
    int kchunks,
    const __half* Af16, int lda,
    const float* Aa, const float* Ab, const float* nt,
    const __half* Bw, int ldb,
    int rowBase, int colBase,
    unsigned char* raw,
    float* cacc)
{
    constexpr int AN  = MROWS / 8;       // per-thread A half2 loads per chunk
    constexpr int BN  = NCOLS / 8;
    constexpr int WMW = MROWS / 16;
    constexpr int WNW = 8 / WMW;
    constexpr int WIDTH = NCOLS / WNW;
    constexpr int NTW = WIDTH / 8;
    const int tid = threadIdx.x, lane = tid & 31, w = tid >> 5;
    const int mrow = (w % WMW) * 16;
    const int ncol = (w / WMW) * WIDTH;
    __half (*sA)[72] = (__half(*)[72])raw;
    __half (*sB)[72] = (__half(*)[72])(raw + MROWS * 72 * 2);

#pragma unroll
    for (int i = 0; i < NTW * 4; i++) cacc[i] = 0.f;

    uint32_t aA[AN], aB[BN];
    auto fetch = [&](int k0) {
#pragma unroll
        for (int i = 0; i < AN; i++) {
            int ww = tid + i * 256;
            int row = ww >> 5, kp = ww & 31;
            int b = rowBase + row;
            int k = k0 + kp * 2;
            __half2 v;
            if (ASRC == SRC_F16) {
                v = *(const __half2*)(Af16 + (size_t)b * lda + k);
            } else if (ASRC == SRC_CONCAT) {
                if (k < DET) {
                    v = *(const __half2*)(Af16 + (size_t)b * DET + k);
                } else {
                    float2 f = *(const float2*)(Aa + (size_t)b * EMBD + (k - DET));
                    v = __floats2half2_rn(f.x, f.y);
                }
            } else { // SRC_INPUT
                float s = nt[b];
                float lo = (k < STO) ? Aa[b * STO + k] * s
                         : ((k < STO + ACTD) ? Ab[b * ACTD + (k - STO)] : 0.f);
                int k1 = k + 1;
                float hi = (k1 < STO) ? Aa[b * STO + k1] * s
                         : ((k1 < STO + ACTD) ? Ab[b * ACTD + (k1 - STO)] : 0.f);
                v = __floats2half2_rn(lo, hi);
            }
            aA[i] = *(uint32_t*)&v;
        }
#pragma unroll
        for (int i = 0; i < BN; i++) {
            int ww = tid + i * 256;
            int row = ww >> 5, kp = ww & 31;
            __half2 v = *(const __half2*)(Bw + (size_t)(colBase + row) * ldb + k0 + kp * 2);
            aB[i] = *(uint32_t*)&v;
        }
    };

    fetch(0);
    for (int c = 0; c < kchunks; c++) {
#pragma unroll
        for (int i = 0; i < AN; i++) {
            int ww = tid + i * 256;
            *(uint32_t*)&sA[ww >> 5][(ww & 31) * 2] = aA[i];
        }
#pragma unroll
        for (int i = 0; i < BN; i++) {
            int ww = tid + i * 256;
            *(uint32_t*)&sB[ww >> 5][(ww & 31) * 2] = aB[i];
        }
        __syncthreads();
#pragma unroll
        for (int kk = 0; kk < 4; kk++) {
            int kb = kk * 16;
            uint32_t afr[4];
            ldm_x4(afr, &sA[mrow + (lane & 15)][kb + ((lane >> 4) << 3)]);
            uint32_t bfr[NTW][2];
#pragma unroll
            for (int nt2 = 0; nt2 < NTW; nt2++)
                ldm_x2(bfr[nt2], &sB[ncol + nt2 * 8 + (lane & 7)][kb + (((lane >> 3) & 1) << 3)]);
#pragma unroll
            for (int nt2 = 0; nt2 < NTW; nt2++)
                mma16816(cacc + nt2 * 4, afr, bfr[nt2]);
        }
        if (c + 1 < kchunks) fetch((c + 1) * 64);
        __syncthreads();
    }
}

// ---------------- prep kernels ----------------------------------------------
__global__ __launch_bounds__(256) void k_prep(
    const float* __restrict__ src, __half* __restrict__ dst,
    int total, int srcK, int dstK, int srcN, int trans)
{
    for (int idx = blockIdx.x * 256 + threadIdx.x; idx < total; idx += gridDim.x * 256) {
        int n = idx / dstK, k = idx % dstK;
        float v = 0.f;
        if (k < srcK)
            v = trans ? src[(size_t)k * srcN + n] : src[(size_t)n * srcK + k];
        dst[idx] = __float2half(v);
    }
}

__global__ __launch_bounds__(256) void k_prep_gru(
    const float* __restrict__ Wih, const float* __restrict__ Whh,
    __half* __restrict__ dst)
{
    int total = 1536 * 512;
    for (int idx = blockIdx.x * 256 + threadIdx.x; idx < total; idx += gridDim.x * 256) {
        int rr = idx / 512, k = idx % 512;
        int jb = rr / 192, rem = rr % 192;
        int gate = rem >> 6, jj = rem & 63;
        int srow = gate * 512 + jb * 64 + jj;
        dst[idx]         = __float2half(Wih[(size_t)srow * 512 + k]);
        dst[total + idx] = __float2half(Whh[(size_t)srow * 512 + k]);
    }
}

// ---------------- step kernels ----------------------------------------------

// K1: x16 = fp16(ELU(cat(stoc*nt, act) @ Wi + bi))   grid(8,16), 64-row tiles
__global__ __launch_bounds__(256) void kg_x(
    const float* __restrict__ stoc_in, const float* __restrict__ act_t,
    const float* __restrict__ nt, const float* __restrict__ bi)
{
    __shared__ __align__(16) unsigned char raw[64 * 72 * 2 + 64 * 72 * 2];
    int rowBase = blockIdx.y * 64, colBase = blockIdx.x * 64;
    float c[16];
    gemm_core<64, 64, SRC_INPUT>(2, nullptr, 0, stoc_in, act_t, nt,
                                 g_Wi16, 128, rowBase, colBase, raw, c);
    int lane = threadIdx.x & 31, w = threadIdx.x >> 5;
    int wm16 = (w & 3) * 16, nc = (w >> 2) * 32;
#pragma unroll
    for (int nt2 = 0; nt2 < 4; nt2++) {
        int col = colBase + nc + nt2 * 8 + (lane & 3) * 2;
#pragma unroll
        for (int h = 0; h < 2; h++) {
            int b = rowBase + wm16 + (lane >> 2) + h * 8;
            float v0 = eluf(c[nt2 * 4 + h * 2]     + bi[col]);
            float v1 = eluf(c[nt2 * 4 + h * 2 + 1] + bi[col + 1]);
            *(__half2*)(g_x16 + (size_t)b * 512 + col) = __floats2half2_rn(v0, v1);
        }
    }
}

// K2: fused GRU, 32-row tiles.  grid(8,32) = 256 CTAs.
__global__ __launch_bounds__(256) void kg_gruf(
    const float* __restrict__ deter_in, const float* __restrict__ nt,
    const float* __restrict__ b_ih, const float* __restrict__ b_hh,
    float* __restrict__ deter_out, float* __restrict__ out_t)
{
    __shared__ __align__(16) unsigned char raw[35840];
    __half (*sAx)[40] = (__half(*)[40])(raw);
    __half (*sAh)[40] = (__half(*)[40])(raw + 2560);
    __half (*sBi)[40] = (__half(*)[40])(raw + 5120);
    __half (*sBh)[40] = (__half(*)[40])(raw + 20480);

    const int tid = threadIdx.x, lane = tid & 31, w = tid >> 5;
    const int wm16 = (w & 1) * 16, wn = w >> 1;           // wn in {0..3}: 48 cols
    const int rowBase = blockIdx.y * 32;
    const int cb192 = blockIdx.x * 192;
    const int jb64  = blockIdx.x * 64;

    float cgi[24], cgh[24];
#pragma unroll
    for (int i = 0; i < 24; i++) { cgi[i] = 0.f; cgh[i] = 0.f; }

    const __half* Bih = g_Wg16;
    const __half* Bhh = g_Wg16 + 1536 * 512;

    uint32_t pAx[2], pAh[2], pBi[12], pBh[12];
#define GRU_FETCH(cc) do { \
        int k0 = (cc) * 32; \
        _Pragma("unroll") \
        for (int i = 0; i < 2; i++) { \
            int ww = tid + i * 256; \
            int row = ww >> 4, kp = ww & 15; \
            int b = rowBase + row, k = k0 + kp * 2; \
            pAx[i] = *(const uint32_t*)(g_x16 + (size_t)b * 512 + k); \
            float2 f = *(const float2*)(deter_in + (size_t)b * DET + k); \
            float s = nt[b]; \
            __half2 v = __floats2half2_rn(f.x * s, f.y * s); \
            pAh[i] = *(uint32_t*)&v; \
        } \
        _Pragma("unroll") \
        for (int i = 0; i < 12; i++) { \
            int ww = tid + i * 256; \
            int row = ww >> 4, kp = ww & 15; \
            int k = k0 + kp * 2; \
            pBi[i] = *(const uint32_t*)(Bih + (size_t)(cb192 + row) * 512 + k); \
            pBh[i] = *(const uint32_t*)(Bhh + (size_t)(cb192 + row) * 512 + k); \
        } \
    } while (0)

    GRU_FETCH(0);
    for (int c = 0; c < 16; c++) {
#pragma unroll
        for (int i = 0; i < 2; i++) {
            int ww = tid + i * 256;
            int row = ww >> 4, kp = ww & 15;
            *(uint32_t*)&sAx[row][kp * 2] = pAx[i];
            *(uint32_t*)&sAh[row][kp * 2] = pAh[i];
        }
#pragma unroll
        for (int i = 0; i < 12; i++) {
            int ww = tid + i * 256;
            int row = ww >> 4, kp = ww & 15;
            *(uint32_t*)&sBi[row][kp * 2] = pBi[i];
            *(uint32_t*)&sBh[row][kp * 2] = pBh[i];
        }
        __syncthreads();
#pragma unroll
        for (int kk = 0; kk < 2; kk++) {
            int kb = kk * 16;
            uint32_t afx[4], afh[4];
            ldm_x4(afx, &sAx[wm16 + (lane & 15)][kb + ((lane >> 4) << 3)]);
            ldm_x4(afh, &sAh[wm16 + (lane & 15)][kb + ((lane >> 4) << 3)]);
#pragma unroll
            for (int nt2 = 0; nt2 < 6; nt2++) {
                uint32_t bf[2];
                ldm_x2(bf, &sBi[wn * 48 + nt2 * 8 + (lane & 7)][kb + (((lane >> 3) & 1) << 3)]);
                mma16816(cgi + nt2 * 4, afx, bf);
                ldm_x2(bf, &sBh[wn * 48 + nt2 * 8 + (lane & 7)][kb + (((lane >> 3) & 1) << 3)]);
                mma16816(cgh + nt2 * 4, afh, bf);
            }
        }
        if (c + 1 < 16) GRU_FETCH(c + 1);
        __syncthreads();
    }

    float (*rS)[65] = (float(*)[65])(raw);
    float (*zS)[65] = (float(*)[65])(raw + 32 * 65 * 4);

#pragma unroll
    for (int nt2 = 0; nt2 < 6; nt2++) {
#pragma unroll
        for (int h = 0; h < 2; h++) {
            int row = wm16 + (lane >> 2) + h * 8;
#pragma unroll
            for (int q = 0; q < 2; q++) {
                int col = wn * 48 + nt2 * 8 + (lane & 3) * 2 + q;
                int gate = col >> 6, jj = col & 63;
                int j = jb64 + jj;
                float gi = cgi[nt2 * 4 + h * 2 + q];
                float gh = cgh[nt2 * 4 + h * 2 + q];
                if (gate == 0)
                    rS[row][jj] = sigm(gi + gh + b_ih[j] + b_hh[j]);
                else if (gate == 1)
                    zS[row][jj] = sigm(gi + gh + b_ih[512 + j] + b_hh[512 + j]);
            }
        }
    }
    __syncthreads();
#pragma unroll
    for (int nt2 = 0; nt2 < 6; nt2++) {
#pragma unroll
        for (int h = 0; h < 2; h++) {
            int row = wm16 + (lane >> 2) + h * 8;
            int b = rowBase + row;
#pragma unroll
            for (int q = 0; q < 2; q++) {
                int col = wn * 48 + nt2 * 8 + (lane & 3) * 2 + q;
                int gate = col >> 6, jj = col & 63;
                if (gate == 2) {
                    int j = jb64 + jj;
                    float inn = cgi[nt2 * 4 + h * 2 + q] + b_ih[1024 + j];
                    float hn  = cgh[nt2 * 4 + h * 2 + q] + b_hh[1024 + j];
                    float r = rS[row][jj];
                    float z = zS[row][jj];
                    float n = tanhf(inn + r * hn);
                    float hv = deter_in[(size_t)b * DET + j] * nt[b];
                    float dn = (1.f - z) * n + z * hv;
                    deter_out[(size_t)b * DET + j] = dn;
                    g_det16[(size_t)b * 512 + j] = __float2half(dn);
                    out_t[(size_t)b * COUT + j] = dn;
                }
            }
        }
    }
}

// K3: mid layers, flat 512-CTA grid, 32-row tiles.
// jobs 0..255: q1 (K=1536, 24 chunks); jobs 256..511: p1 (K=512, 8 chunks).
__global__ __launch_bounds__(256) void kg_mid(
    const float* __restrict__ emb_t,
    const float* __restrict__ bp1, const float* __restrict__ bq1)
{
    __shared__ __align__(16) unsigned char raw[32 * 72 * 2 + 64 * 72 * 2];
    int job = blockIdx.x;
    int z = (job < 256) ? 1 : 0;
    int j2 = z ? job : job - 256;
    int rowBase = (j2 >> 3) * 32, colBase = (j2 & 7) * 64;
    float c[8];
    if (z)
        gemm_core<32, 64, SRC_CONCAT>(24, g_det16, 512, emb_t, nullptr, nullptr,
                                      g_Wq116, 1536, rowBase, colBase, raw, c);
    else
        gemm_core<32, 64, SRC_F16>(8, g_det16, 512, nullptr, nullptr, nullptr,
                                   g_Wp116, 512, rowBase, colBase, raw, c);
    const float* bia = z ? bq1 : bp1;
    __half* outp = z ? g_q116 : g_p116;
    int lane = threadIdx.x & 31, w = threadIdx.x >> 5;
    int wm16 = (w & 1) * 16, nc = (w >> 1) * 16;
#pragma unroll
    for (int nt2 = 0; nt2 < 2; nt2++) {
        int col = colBase + nc + nt2 * 8 + (lane & 3) * 2;
#pragma unroll
        for (int h = 0; h < 2; h++) {
            int b = rowBase + wm16 + (lane >> 2) + h * 8;
            float v0 = eluf(c[nt2 * 4 + h * 2]     + bia[col]);
            float v1 = eluf(c[nt2 * 4 + h * 2 + 1] + bia[col + 1]);
            *(__half2*)(outp + (size_t)b * 512 + col) = __floats2half2_rn(v0, v1);
        }
    }
}

// K4: heads, flat 64-CTA grid, 32-row tiles. bid>>5 = z (0 prior, 1 posterior).
__global__ __launch_bounds__(256) void kg_head(
    const float* __restrict__ bp2, const float* __restrict__ bq2,
    const float* __restrict__ eps_p, const float* __restrict__ eps_q,
    float* __restrict__ out_t, float* __restrict__ stoc_out)
{
    __shared__ __align__(16) unsigned char raw[32 * 72 * 2 + 128 * 72 * 2];
    int z = blockIdx.x >> 5;
    int rowBase = (blockIdx.x & 31) * 32;
    float c[16];
    if (z)
        gemm_core<32, 128, SRC_F16>(8, g_q116, 512, nullptr, nullptr, nullptr,
                                    g_Wq216, 512, rowBase, 0, raw, c);
    else
        gemm_core<32, 128, SRC_F16>(8, g_p116, 512, nullptr, nullptr, nullptr,
                                    g_Wp216, 512, rowBase, 0, raw, c);
    const float* b2  = z ? bq2 : bp2;
    const float* eps = z ? eps_q : eps_p;
    const int obase  = z ? (DET + 3 * STO) : DET;
    int lane = threadIdx.x & 31, w = threadIdx.x >> 5;
    int wm16 = (w & 1) * 16, nc = (w >> 1) * 32;

    float (*Ss)[65] = (float(*)[65])(raw);

    // pass 1: std columns (col >= 64)
#pragma unroll
    for (int nt2 = 0; nt2 < 4; nt2++) {
#pragma unroll
        for (int h = 0; h < 2; h++) {
            int row = wm16 + (lane >> 2) + h * 8;
            int b = rowBase + row;
#pragma unroll
            for (int q = 0; q < 2; q++) {
                int col = nc + nt2 * 8 + (lane & 3) * 2 + q;
                if (col >= 64) {
                    int ii = col - 64;
                    float s = softp(c[nt2 * 4 + h * 2 + q] + b2[col]) + 0.1f;
                    Ss[row][ii] = s;
                    out_t[(size_t)b * COUT + obase + STO + ii] = s;
                }
            }
        }
    }
    __syncthreads();
    // pass 2: mean columns + sample
#pragma unroll
    for (int nt2 = 0; nt2 < 4; nt2++) {
#pragma unroll
        for (int h = 0; h < 2; h++) {
            int row = wm16 + (lane >> 2) + h * 8;
            int b = rowBase + row;
#pragma unroll
            for (int q = 0; q < 2; q++) {
                int col = nc + nt2 * 8 + (lane & 3) * 2 + q;
                if (col < 64) {
                    float m = c[nt2 * 4 + h * 2 + q] + b2[col];
                    float s = Ss[row][col];
                    float st = m + s * eps[b * STO + col];
                    size_t base = (size_t)b * COUT + obase;
                    out_t[base + col]           = m;
                    out_t[base + 2 * STO + col] = st;
                    if (z) stoc_out[b * STO + col] = st;
                }
            }
        }
    }
}

// ---------------------------------------------------------------------------
extern "C" void kernel_launch(void* const* d_in, const int* in_sizes, int n_in,
                              void* d_out, int out_size)
{
    const float* actions    = (const float*)d_in[0];
    const float* nonterm    = (const float*)d_in[1];
    const float* emb        = (const float*)d_in[2];
    const float* init_deter = (const float*)d_in[3];
    const float* init_stoc  = (const float*)d_in[4];
    const float* noise_p    = (const float*)d_in[5];
    const float* noise_q    = (const float*)d_in[6];
    const float* Wi   = (const float*)d_in[7];
    const float* bi   = (const float*)d_in[8];
    const float* W_ih = (const float*)d_in[9];
    const float* W_hh = (const float*)d_in[10];
    const float* b_ih = (const float*)d_in[11];
    const float* b_hh = (const float*)d_in[12];
    const float* Wp1  = (const float*)d_in[13];
    const float* bp1  = (const float*)d_in[14];
    const float* Wp2  = (const float*)d_in[15];
    const float* bp2  = (const float*)d_in[16];
    const float* Wq1  = (const float*)d_in[17];
    const float* bq1  = (const float*)d_in[18];
    const float* Wq2  = (const float*)d_in[19];
    const float* bq2  = (const float*)d_in[20];
    float* out = (float*)d_out;

    __half *wi16, *wg16, *wp116, *wq116, *wp216, *wq216;
    float  *deterBuf, *stocBuf;
    cudaGetSymbolAddress((void**)&wi16,  g_Wi16);
    cudaGetSymbolAddress((void**)&wg16,  g_Wg16);
    cudaGetSymbolAddress((void**)&wp116, g_Wp116);
    cudaGetSymbolAddress((void**)&wq116, g_Wq116);
    cudaGetSymbolAddress((void**)&wp216, g_Wp216);
    cudaGetSymbolAddress((void**)&wq216, g_Wq216);
    cudaGetSymbolAddress((void**)&deterBuf, g_deter);
    cudaGetSymbolAddress((void**)&stocBuf,  g_stoc);

    auto prep = [&](const float* src, __half* dst, int N, int srcK, int dstK, int srcN, int trans) {
        int total = N * dstK;
        k_prep<<<(total + 255) / 256, 256>>>(src, dst, total, srcK, dstK, srcN, trans);
    };
    prep(Wi,  wi16,  512, 70,   128,  512, 1);
    prep(Wp1, wp116, 512, 512,  512,  512, 1);
    prep(Wq1, wq116, 512, 1536, 1536, 512, 1);
    prep(Wp2, wp216, 128, 512,  512,  128, 1);
    prep(Wq2, wq216, 128, 512,  512,  128, 1);
    k_prep_gru<<<1024, 256>>>(W_ih, W_hh, wg16);

    for (int t = 0; t < TT; t++) {
        const float* stoc_in  = t ? stocBuf  + ((t + 1) & 1) * BBATCH * STO : init_stoc;
        const float* deter_in = t ? deterBuf + ((t + 1) & 1) * BBATCH * DET : init_deter;
        float* deter_out = deterBuf + (t & 1) * BBATCH * DET;
        float* stoc_out  = stocBuf  + (t & 1) * BBATCH * STO;
        const float* nt_t  = nonterm + (size_t)t * BBATCH;
        const float* act_t = actions + (size_t)t * BBATCH * ACTD;
        const float* emb_t = emb     + (size_t)t * BBATCH * EMBD;
        float* out_t = out + (size_t)t * BBATCH * COUT;

        kg_x   <<<dim3(8, 16), 256>>>(stoc_in, act_t, nt_t, bi);
        kg_gruf<<<dim3(8, 32), 256>>>(deter_in, nt_t, b_ih, b_hh,
                                      deter_out, out_t);
        kg_mid <<<512, 256>>>(emb_t, bp1, bq1);
        kg_head<<<64, 256>>>(bp2, bq2,
                             noise_p + (size_t)t * BBATCH * STO,
                             noise_q + (size_t)t * BBATCH * STO,
                             out_t, stoc_out);
    }
}